// round 6
// baseline (speedup 1.0000x reference)
#include <cuda_runtime.h>
#include <cuda_fp16.h>
#include <cstdint>
#include <math.h>

namespace {
constexpr int Tn = 4096, Hd = 1024, Fd = 4096, F2d = 2048, Ex = 8;
constexpr int GST = 4;                   // pipeline stages
constexpr int STB = 32768;               // bytes/stage: A 16KB + B 16KB
constexpr int GSMEM = GST * STB + 512;   // + srow
}
static constexpr size_t SZF = (size_t)Tn * Fd;
static constexpr size_t SZT = (size_t)Tn * F2d;
static constexpr size_t SZD = (size_t)Tn * Hd;

__device__ __half g_nx[(size_t)Tn * Hd];
__device__ __half g_h1[(size_t)Ex * Tn * Fd];
__device__ __half g_h2[(size_t)Ex * Tn * Fd];
__device__ __half g_t1[(size_t)2 * Tn * F2d];
__device__ float  g_dn[(size_t)Ex * Tn * Hd];
__device__ float  g_w2[Tn * 2];
__device__ int    g_list[Ex * Tn];
__device__ int    g_cnt[Ex];
__device__ int    g_te[Tn * 2];
__device__ int    g_tp[Tn * 2];
__device__ __half g_upWt [(size_t)Ex * Fd * Hd];
__device__ __half g_dnWt [(size_t)Ex * Hd * Fd];
__device__ __half g_s0Wt [(size_t)2 * Fd * Fd];
__device__ __half g_s1aWt[(size_t)2 * F2d * Fd];
__device__ __half g_s1bWt[(size_t)2 * Fd * F2d];
__device__ __half g_s2Wt [(size_t)2 * Fd * Fd];

__device__ __forceinline__ float gelu_f(float v) {
    return 0.5f * v * (1.0f + erff(v * 0.70710678118654752f));
}
__device__ __forceinline__ void cpa16(uint32_t dst, const void* src, bool pred) {
    int sz = pred ? 16 : 0;
    asm volatile("cp.async.cg.shared.global [%0], [%1], 16, %2;\n" :: "r"(dst), "l"(src), "r"(sz));
}
__device__ __forceinline__ uint32_t smem_u32(const void* p) {
    uint32_t a;
    asm("{ .reg .u64 t; cvta.to.shared.u64 t, %1; cvt.u32.u64 %0, t; }" : "=r"(a) : "l"(p));
    return a;
}
__device__ __forceinline__ uint32_t sw128(uint32_t o) { return o ^ ((o >> 3) & 0x70); }

__global__ void zero_cnt_kernel() { if (threadIdx.x < Ex) g_cnt[threadIdx.x] = 0; }

// ---------------- LN + router + scatter (one block per token) -------------
__global__ __launch_bounds__(256, 1) void ln_router_kernel(
    const float* __restrict__ x, const float* __restrict__ lng,
    const float* __restrict__ lnb, const float* __restrict__ rw)
{
    int t = blockIdx.x, tid = threadIdx.x, lane = tid & 31, wid = tid >> 5;
    __shared__ float ss[8], sq[8], sl[8][8], slog[8];
    float4 v = reinterpret_cast<const float4*>(x + (size_t)t * Hd)[tid];
    float s = v.x + v.y + v.z + v.w;
    float q = v.x * v.x + v.y * v.y + v.z * v.z + v.w * v.w;
    #pragma unroll
    for (int o = 16; o; o >>= 1) { s += __shfl_xor_sync(~0u, s, o); q += __shfl_xor_sync(~0u, q, o); }
    if (lane == 0) { ss[wid] = s; sq[wid] = q; }
    __syncthreads();
    if (tid == 0) {
        float S = 0.f, Q = 0.f;
        for (int i = 0; i < 8; i++) { S += ss[i]; Q += sq[i]; }
        ss[0] = S; sq[0] = Q;
    }
    __syncthreads();
    float mean = ss[0] * (1.0f / Hd);
    float var = fmaxf(sq[0] * (1.0f / Hd) - mean * mean, 0.0f);
    float rs = rsqrtf(var + 1e-5f);
    float4 g4 = reinterpret_cast<const float4*>(lng)[tid];
    float4 b4 = reinterpret_cast<const float4*>(lnb)[tid];
    float n0v = (v.x - mean) * rs * g4.x + b4.x;
    float n1v = (v.y - mean) * rs * g4.y + b4.y;
    float n2v = (v.z - mean) * rs * g4.z + b4.z;
    float n3v = (v.w - mean) * rs * g4.w + b4.w;
    __half2* nh = reinterpret_cast<__half2*>(g_nx + (size_t)t * Hd);
    nh[tid * 2] = __floats2half2_rn(n0v, n1v);
    nh[tid * 2 + 1] = __floats2half2_rn(n2v, n3v);

    float nv[4] = {n0v, n1v, n2v, n3v};
    float acc[8] = {0.f,0.f,0.f,0.f,0.f,0.f,0.f,0.f};
    int i0 = tid * 4;
    #pragma unroll
    for (int j = 0; j < 4; j++) {
        const float4* rr = reinterpret_cast<const float4*>(rw + (size_t)(i0 + j) * Ex);
        float4 r0 = rr[0], r1 = rr[1];
        acc[0] += nv[j] * r0.x; acc[1] += nv[j] * r0.y;
        acc[2] += nv[j] * r0.z; acc[3] += nv[j] * r0.w;
        acc[4] += nv[j] * r1.x; acc[5] += nv[j] * r1.y;
        acc[6] += nv[j] * r1.z; acc[7] += nv[j] * r1.w;
    }
    #pragma unroll
    for (int e = 0; e < 8; e++)
        #pragma unroll
        for (int o = 16; o; o >>= 1) acc[e] += __shfl_xor_sync(~0u, acc[e], o);
    if (lane == 0)
        #pragma unroll
        for (int e = 0; e < 8; e++) sl[wid][e] = acc[e];
    __syncthreads();
    if (tid < 8) {
        float L = 0.f;
        for (int w = 0; w < 8; w++) L += sl[w][tid];
        slog[tid] = L;
    }
    __syncthreads();
    if (tid == 0) {
        float p[8], mx = slog[0];
        for (int e = 1; e < 8; e++) mx = fmaxf(mx, slog[e]);
        float Z = 0.f;
        for (int e = 0; e < 8; e++) { p[e] = expf(slog[e] - mx); Z += p[e]; }
        float iZ = 1.0f / Z;
        for (int e = 0; e < 8; e++) p[e] *= iZ;
        int i1 = 0;
        for (int e = 1; e < 8; e++) if (p[e] > p[i1]) i1 = e;
        int i2 = (i1 == 0) ? 1 : 0;
        for (int e = 0; e < 8; e++) if (e != i1 && p[e] > p[i2]) i2 = e;
        float iw = 1.0f / (p[i1] + p[i2]);
        g_w2[2*t] = p[i1] * iw; g_w2[2*t+1] = p[i2] * iw;
        int p1 = atomicAdd(&g_cnt[i1], 1); g_list[i1 * Tn + p1] = t;
        int p2 = atomicAdd(&g_cnt[i2], 1); g_list[i2 * Tn + p2] = t;
        g_te[2*t] = i1; g_te[2*t+1] = i2;
        g_tp[2*t] = p1; g_tp[2*t+1] = p2;
    }
}

// ------------- transpose + fp32->fp16: Wt[n][k] = W[k][n] ------------------
__global__ __launch_bounds__(256, 1) void transp_kernel(
    const float* __restrict__ W, __half* __restrict__ Wt, int K, int N)
{
    __shared__ float tile[32][33];
    const float* src = W + (size_t)blockIdx.z * K * N;
    __half* dst = Wt + (size_t)blockIdx.z * K * N;
    int kb = blockIdx.y * 32, nb = blockIdx.x * 32;
    int tx = threadIdx.x & 31, ty = threadIdx.x >> 5;
    #pragma unroll
    for (int i = 0; i < 4; i++)
        tile[ty + 8 * i][tx] = src[(size_t)(kb + ty + 8 * i) * N + nb + tx];
    __syncthreads();
    #pragma unroll
    for (int i = 0; i < 4; i++)
        dst[(size_t)(nb + ty + 8 * i) * K + kb + tx] = __float2half_rn(tile[tx][ty + 8 * i]);
}

// -------- fp16 mma.sync m16n8k16 GEMM, ldmatrix + 4-stage cp.async --------
enum { M_UP = 0, M_S0, M_S1A, M_S1B, M_S2, M_DOWN };

template <int MODE>
__global__ __launch_bounds__(256, 1) void gemm16_kernel(
    const __half* __restrict__ Bt, const float* __restrict__ biasb)
{
    constexpr bool GATHER  = (MODE == M_UP);
    constexpr bool DO_GELU = (MODE == M_UP || MODE == M_S1A || MODE == M_S2);
    constexpr bool OUT_F32 = (MODE == M_DOWN);
    constexpr int  e0    = (MODE == M_S1A || MODE == M_S1B) ? 1 : (MODE == M_S2 ? 2 : 0);
    constexpr int  estep = (MODE == M_UP || MODE == M_DOWN) ? 1 : 4;
    constexpr int  Kd    = (MODE == M_UP) ? Hd : (MODE == M_S1B ? F2d : Fd);
    constexpr int  Nf    = (MODE == M_S1A) ? F2d : (MODE == M_DOWN ? Hd : Fd);
    constexpr int  KT    = Kd / 64;

    int z = blockIdx.z, e = e0 + estep * z;
    int M = g_cnt[e];
    int m0 = blockIdx.y * 128;
    if (m0 >= M) return;
    int n0 = blockIdx.x * 128;

    const __half* A; void* Cv; int ldc;
    if constexpr (MODE == M_UP)       { A = g_nx;                   Cv = g_h1 + (size_t)e * SZF; ldc = Fd;  }
    else if constexpr (MODE == M_S0)  { A = g_h1 + (size_t)e * SZF; Cv = g_h2 + (size_t)e * SZF; ldc = Fd;  }
    else if constexpr (MODE == M_S1A) { A = g_h1 + (size_t)e * SZF; Cv = g_t1 + (size_t)z * SZT; ldc = F2d; }
    else if constexpr (MODE == M_S1B) { A = g_t1 + (size_t)z * SZT; Cv = g_h2 + (size_t)e * SZF; ldc = Fd;  }
    else if constexpr (MODE == M_S2)  { A = g_h1 + (size_t)e * SZF; Cv = g_h2 + (size_t)e * SZF; ldc = Fd;  }
    else { A = (((e & 3) == 3) ? g_h1 : g_h2) + (size_t)e * SZF;    Cv = g_dn + (size_t)e * SZD; ldc = Hd;  }

    const __half* Bp = Bt + (size_t)z * Nf * Kd + (size_t)n0 * Kd;
    const float*  bp = biasb + (size_t)z * Nf + n0;

    extern __shared__ char smem[];
    uint32_t sb = smem_u32(smem);
    int* srow = (int*)(smem + GST * STB);
    int tid = threadIdx.x, lane = tid & 31, wid = tid >> 5;

    if (GATHER) {
        if (tid < 128) {
            int r = m0 + tid;
            srow[tid] = (r < M) ? g_list[e * Tn + r] : 0;
        }
        __syncthreads();
    }

    // --- cp.async mapping: 4 A chunks + 4 B chunks of 16B per thread ------
    int cj = tid & 7;                 // 16B chunk within 128B row
    const __half* asrc[4]; bool aval[4];
    const __half* bsrc[4];
    uint32_t soff[4];
    #pragma unroll
    for (int i = 0; i < 4; i++) {
        int row = (tid >> 3) + 32 * i;          // 0..127
        int r = m0 + row;
        aval[i] = (r < M);
        int srci = GATHER ? (aval[i] ? srow[row] : 0) : (aval[i] ? r : 0);
        asrc[i] = A + (size_t)srci * Kd + cj * 8;
        bsrc[i] = Bp + (size_t)row * Kd + cj * 8;
        soff[i] = sw128((uint32_t)row * 128 + cj * 16);
    }

    auto issue = [&](int kt, int slot) {
        if (kt < KT) {
            uint32_t base = sb + slot * STB;
            int ko = kt * 64;
            #pragma unroll
            for (int i = 0; i < 4; i++) cpa16(base + soff[i], asrc[i] + ko, aval[i]);
            #pragma unroll
            for (int i = 0; i < 4; i++) cpa16(base + 16384 + soff[i], bsrc[i] + ko, true);
        }
        asm volatile("cp.async.commit_group;\n" ::: "memory");
    };
    issue(0, 0); issue(1, 1); issue(2, 2);

    // --- warp tiling: 8 warps (4 wm x 2 wn), warp tile 32m x 64n -----------
    int wm = wid >> 1, wn = wid & 1;
    // A ldmatrix lane addressing (per mi): row/byte pattern, swizzle-split
    int aq = lane >> 3;
    int arow_l = (lane & 7) + (aq & 1) * 8;    // 0..15 within 16-row block
    int abyte_l = (aq >> 1) * 16;              // 0 or 16
    // B ldmatrix lane addressing (per nj pair of 16 n-rows)
    int brow_l = (aq >> 1) * 8 + (lane & 7);   // 0..15 within 16-n block
    int bbyte_l = (aq & 1) * 16;

    float acc[2][8][4];
    #pragma unroll
    for (int a = 0; a < 2; a++)
        #pragma unroll
        for (int b = 0; b < 8; b++)
            #pragma unroll
            for (int c = 0; c < 4; c++) acc[a][b][c] = 0.f;

    // precompute per-thread row bases + swizzle xor
    uint32_t arb[2], axr[2];
    #pragma unroll
    for (int mi = 0; mi < 2; mi++) {
        int r = wm * 32 + mi * 16 + arow_l;
        arb[mi] = (uint32_t)r * 128;
        axr[mi] = (uint32_t)(r & 7) * 16;
    }
    uint32_t brb[4], bxr[4];
    #pragma unroll
    for (int nj = 0; nj < 4; nj++) {
        int n = wn * 64 + nj * 16 + brow_l;
        brb[nj] = (uint32_t)n * 128;
        bxr[nj] = (uint32_t)(n & 7) * 16;
    }

    for (int kt = 0; kt < KT; kt++) {
        asm volatile("cp.async.wait_group 2;\n" ::: "memory");
        __syncthreads();
        issue(kt + 3, (kt + 3) & 3);

        uint32_t Ab = sb + (kt & 3) * STB;
        uint32_t Bb = Ab + 16384;
        #pragma unroll
        for (int kk = 0; kk < 4; kk++) {
            uint32_t kb = (uint32_t)kk * 32;
            uint32_t af[2][4];
            #pragma unroll
            for (int mi = 0; mi < 2; mi++) {
                uint32_t addr = Ab + arb[mi] + (((kb + abyte_l)) ^ axr[mi]);
                asm volatile("ldmatrix.sync.aligned.m8n8.x4.shared.b16 {%0,%1,%2,%3}, [%4];"
                             : "=r"(af[mi][0]), "=r"(af[mi][1]), "=r"(af[mi][2]), "=r"(af[mi][3])
                             : "r"(addr));
            }
            uint32_t bf[8][2];
            #pragma unroll
            for (int nj = 0; nj < 4; nj++) {
                uint32_t addr = Bb + brb[nj] + (((kb + bbyte_l)) ^ bxr[nj]);
                uint32_t r0, r1, r2, r3;
                asm volatile("ldmatrix.sync.aligned.m8n8.x4.shared.b16 {%0,%1,%2,%3}, [%4];"
                             : "=r"(r0), "=r"(r1), "=r"(r2), "=r"(r3) : "r"(addr));
                bf[2*nj][0] = r0; bf[2*nj][1] = r1;
                bf[2*nj+1][0] = r2; bf[2*nj+1][1] = r3;
            }
            #pragma unroll
            for (int mi = 0; mi < 2; mi++)
                #pragma unroll
                for (int ni = 0; ni < 8; ni++)
                    asm volatile(
                        "mma.sync.aligned.m16n8k16.row.col.f32.f16.f16.f32 "
                        "{%0,%1,%2,%3}, {%4,%5,%6,%7}, {%8,%9}, {%0,%1,%2,%3};\n"
                        : "+f"(acc[mi][ni][0]), "+f"(acc[mi][ni][1]),
                          "+f"(acc[mi][ni][2]), "+f"(acc[mi][ni][3])
                        : "r"(af[mi][0]), "r"(af[mi][1]), "r"(af[mi][2]), "r"(af[mi][3]),
                          "r"(bf[ni][0]), "r"(bf[ni][1]));
        }
    }

    // --- epilogue: +bias, optional exact gelu ------------------------------
    int qq = lane & 3, lg = lane >> 2;
    #pragma unroll
    for (int mi = 0; mi < 2; mi++) {
        #pragma unroll
        for (int hf = 0; hf < 2; hf++) {
            int r = m0 + wm * 32 + mi * 16 + lg + hf * 8;
            if (r < M) {
                #pragma unroll
                for (int ni = 0; ni < 8; ni++) {
                    int c = wn * 64 + ni * 8 + 2 * qq;
                    float v0 = acc[mi][ni][hf * 2 + 0] + bp[c];
                    float v1 = acc[mi][ni][hf * 2 + 1] + bp[c + 1];
                    if (DO_GELU) { v0 = gelu_f(v0); v1 = gelu_f(v1); }
                    if (OUT_F32) {
                        float* crow = (float*)Cv + (size_t)r * ldc + n0;
                        *reinterpret_cast<float2*>(crow + c) = make_float2(v0, v1);
                    } else {
                        __half* crow = (__half*)Cv + (size_t)r * ldc + n0;
                        *reinterpret_cast<__half2*>(crow + c) = __floats2half2_rn(v0, v1);
                    }
                }
            }
        }
    }
}

// ---------------- row LayerNorm over F on fp16 (optional gelu) ------------
template <bool DO_GELU>
__global__ __launch_bounds__(256, 1) void rowln16_kernel(
    int e0, const float* __restrict__ gg, const float* __restrict__ bb)
{
    int z = blockIdx.y, e = e0 + 4 * z;
    int row = blockIdx.x;
    if (row >= g_cnt[e]) return;
    __half* p = g_h2 + (size_t)e * SZF + (size_t)row * Fd;
    int tid = threadIdx.x, lane = tid & 31, wid = tid >> 5;
    __shared__ float ss[8], sq[8];
    uint4* p4 = reinterpret_cast<uint4*>(p);
    uint4 u[2];
    float vals[16];
    float s = 0.f, q = 0.f;
    #pragma unroll
    for (int i = 0; i < 2; i++) {
        u[i] = p4[tid + 256 * i];
        const __half2* h2 = reinterpret_cast<const __half2*>(&u[i]);
        #pragma unroll
        for (int j = 0; j < 4; j++) {
            float2 f = __half22float2(h2[j]);
            vals[i * 8 + 2 * j] = f.x; vals[i * 8 + 2 * j + 1] = f.y;
            s += f.x + f.y; q += f.x * f.x + f.y * f.y;
        }
    }
    #pragma unroll
    for (int o = 16; o; o >>= 1) { s += __shfl_xor_sync(~0u, s, o); q += __shfl_xor_sync(~0u, q, o); }
    if (lane == 0) { ss[wid] = s; sq[wid] = q; }
    __syncthreads();
    if (tid == 0) {
        float S = 0.f, Q = 0.f;
        for (int i = 0; i < 8; i++) { S += ss[i]; Q += sq[i]; }
        ss[0] = S; sq[0] = Q;
    }
    __syncthreads();
    float mean = ss[0] * (1.0f / Fd);
    float var = fmaxf(sq[0] * (1.0f / Fd) - mean * mean, 0.0f);
    float rs = rsqrtf(var + 1e-5f);
    const float* gr = gg + (size_t)z * Fd;
    const float* br = bb + (size_t)z * Fd;
    #pragma unroll
    for (int i = 0; i < 2; i++) {
        __half2 out[4];
        #pragma unroll
        for (int j = 0; j < 4; j++) {
            int idx = (tid + 256 * i) * 8 + 2 * j;
            float o0 = (vals[i * 8 + 2 * j]     - mean) * rs * gr[idx]     + br[idx];
            float o1 = (vals[i * 8 + 2 * j + 1] - mean) * rs * gr[idx + 1] + br[idx + 1];
            if (DO_GELU) { o0 = gelu_f(o0); o1 = gelu_f(o1); }
            out[j] = __floats2half2_rn(o0, o1);
        }
        p4[tid + 256 * i] = *reinterpret_cast<uint4*>(out);
    }
}

// ------------------------- combine epilogue -------------------------------
__global__ __launch_bounds__(256, 1) void combine_kernel(
    const float* __restrict__ x, float* __restrict__ y)
{
    int t = blockIdx.x, tid = threadIdx.x;
    int e1 = g_te[2*t], e2 = g_te[2*t+1];
    int p1 = g_tp[2*t], p2 = g_tp[2*t+1];
    float w1 = g_w2[2*t], w2 = g_w2[2*t+1];
    const float4* xv = reinterpret_cast<const float4*>(x + (size_t)t * Hd);
    const float4* d1 = reinterpret_cast<const float4*>(g_dn + (size_t)e1 * SZD + (size_t)p1 * Hd);
    const float4* d2 = reinterpret_cast<const float4*>(g_dn + (size_t)e2 * SZD + (size_t)p2 * Hd);
    float4 a = xv[tid], b = d1[tid], c = d2[tid], o;
    o.x = a.x + w1 * b.x + w2 * c.x;
    o.y = a.y + w1 * b.y + w2 * c.y;
    o.z = a.z + w1 * b.z + w2 * c.z;
    o.w = a.w + w1 * b.w + w2 * c.w;
    reinterpret_cast<float4*>(y + (size_t)t * Hd)[tid] = o;
}

// ---------------------------------------------------------------------------
extern "C" void kernel_launch(void* const* d_in, const int* in_sizes, int n_in,
                              void* d_out, int out_size)
{
    const float* x        = (const float*)d_in[0];
    const float* ln_g     = (const float*)d_in[1];
    const float* ln_b     = (const float*)d_in[2];
    const float* router_w = (const float*)d_in[3];
    const float* up_W     = (const float*)d_in[4];
    const float* up_b     = (const float*)d_in[5];
    const float* down_W   = (const float*)d_in[6];
    const float* down_b   = (const float*)d_in[7];
    const float* spec0_W  = (const float*)d_in[8];
    const float* spec0_b  = (const float*)d_in[9];
    const float* ln0_g    = (const float*)d_in[10];
    const float* ln0_b    = (const float*)d_in[11];
    const float* spec1a_W = (const float*)d_in[12];
    const float* spec1a_b = (const float*)d_in[13];
    const float* spec1b_W = (const float*)d_in[14];
    const float* spec1b_b = (const float*)d_in[15];
    const float* ln1_g    = (const float*)d_in[16];
    const float* ln1_b    = (const float*)d_in[17];
    const float* spec2_W  = (const float*)d_in[18];
    const float* spec2_b  = (const float*)d_in[19];
    float* y = (float*)d_out;

    static bool attr_done = false;
    if (!attr_done) {
        cudaFuncSetAttribute((const void*)gemm16_kernel<M_UP>,   cudaFuncAttributeMaxDynamicSharedMemorySize, GSMEM);
        cudaFuncSetAttribute((const void*)gemm16_kernel<M_S0>,   cudaFuncAttributeMaxDynamicSharedMemorySize, GSMEM);
        cudaFuncSetAttribute((const void*)gemm16_kernel<M_S1A>,  cudaFuncAttributeMaxDynamicSharedMemorySize, GSMEM);
        cudaFuncSetAttribute((const void*)gemm16_kernel<M_S1B>,  cudaFuncAttributeMaxDynamicSharedMemorySize, GSMEM);
        cudaFuncSetAttribute((const void*)gemm16_kernel<M_S2>,   cudaFuncAttributeMaxDynamicSharedMemorySize, GSMEM);
        cudaFuncSetAttribute((const void*)gemm16_kernel<M_DOWN>, cudaFuncAttributeMaxDynamicSharedMemorySize, GSMEM);
        attr_done = true;
    }

    zero_cnt_kernel<<<1, 32>>>();
    ln_router_kernel<<<Tn, 256>>>(x, ln_g, ln_b, router_w);

    transp_kernel<<<dim3(Fd/32,  Hd/32, 8), 256>>>(up_W,     g_upWt,  Hd,  Fd);
    transp_kernel<<<dim3(Hd/32,  Fd/32, 8), 256>>>(down_W,   g_dnWt,  Fd,  Hd);
    transp_kernel<<<dim3(Fd/32,  Fd/32, 2), 256>>>(spec0_W,  g_s0Wt,  Fd,  Fd);
    transp_kernel<<<dim3(F2d/32, Fd/32, 2), 256>>>(spec1a_W, g_s1aWt, Fd,  F2d);
    transp_kernel<<<dim3(Fd/32, F2d/32, 2), 256>>>(spec1b_W, g_s1bWt, F2d, Fd);
    transp_kernel<<<dim3(Fd/32,  Fd/32, 2), 256>>>(spec2_W,  g_s2Wt,  Fd,  Fd);

    gemm16_kernel<M_UP>  <<<dim3(Fd/128,  Tn/128, 8), 256, GSMEM>>>(g_upWt,  up_b);
    gemm16_kernel<M_S0>  <<<dim3(Fd/128,  Tn/128, 2), 256, GSMEM>>>(g_s0Wt,  spec0_b);
    gemm16_kernel<M_S1A> <<<dim3(F2d/128, Tn/128, 2), 256, GSMEM>>>(g_s1aWt, spec1a_b);
    gemm16_kernel<M_S2>  <<<dim3(Fd/128,  Tn/128, 2), 256, GSMEM>>>(g_s2Wt,  spec2_b);
    rowln16_kernel<true> <<<dim3(Tn, 2), 256>>>(0, ln0_g, ln0_b);
    gemm16_kernel<M_S1B> <<<dim3(Fd/128,  Tn/128, 2), 256, GSMEM>>>(g_s1bWt, spec1b_b);
    rowln16_kernel<false><<<dim3(Tn, 2), 256>>>(1, ln1_g, ln1_b);
    gemm16_kernel<M_DOWN><<<dim3(Hd/128,  Tn/128, 8), 256, GSMEM>>>(g_dnWt,  down_b);

    combine_kernel<<<Tn, 256>>>(x, y);
}